// round 7
// baseline (speedup 1.0000x reference)
#include <cuda_runtime.h>

// ---------------------------------------------------------------------------
// DummyGCN4: 4-layer GCN, output = h3[node 1] only.
// R7: backward-slice (R2/R6 structure, 7 kernels) + Programmatic Dependent
// Launch pipelining. Each kernel prefetches its READ-ONLY inputs (dst/src/
// in_feat) into registers, triggers its successor, then griddepcontrol.wait's
// for its predecessor before consuming predecessor-written state (bitmaps,
// lists, aggs). This overlaps each scan's memory latency with the previous
// kernel's execution, collapsing the 4x ~9us serial scan chain.
// ---------------------------------------------------------------------------

#define MAXN 50048
#define BMW  1568
#define OUT_NODE 1
#define E1CAP  8192
#define E2CAP  32768
#define EBCAP  262144

__device__ unsigned g_B0[BMW], g_B1[BMW], g_B2[BMW];
__device__ int   g_list1[MAXN], g_list2[MAXN];
__device__ int   g_cnt1, g_cnt2;
__device__ int   g_e1s[E1CAP];                 __device__ int g_e1n;
__device__ int   g_e2s[E2CAP],  g_e2d[E2CAP];  __device__ int g_e2n;
__device__ int   g_ebs[EBCAP],  g_ebd[EBCAP];  __device__ int g_ebn;
__device__ float g_agg0[MAXN];
__device__ float g_agg1[(size_t)MAXN * 64];
__device__ float g_x2[(size_t)MAXN * 64];
__device__ float g_agg2[(size_t)MAXN * 64];
__device__ float g_x3[MAXN];

#define PDL_TRIGGER() asm volatile("griddepcontrol.launch_dependents;" ::: "memory")
#define PDL_WAIT()    asm volatile("griddepcontrol.wait;" ::: "memory")
#define KEEPI4(v) asm volatile("" :: "r"((v).x), "r"((v).y), "r"((v).z), "r"((v).w))
#define KEEPF(v)  asm volatile("" :: "f"(v))

__device__ __forceinline__ float lrelu(float x) { return x >= 0.f ? x : 0.01f * x; }
__device__ __forceinline__ bool tb(const unsigned* b, int i) {
    return (b[i >> 5] >> (i & 31)) & 1u;
}
__device__ __forceinline__ void zero64(float* a) {
    float4 z = make_float4(0.f, 0.f, 0.f, 0.f);
    float4* a4 = (float4*)a;
    #pragma unroll
    for (int j = 0; j < 16; j++) a4[j] = z;
}

// ---- hit handlers (post-wait only) ----
__device__ __forceinline__ void hit32v(int s) {
    int p = atomicAdd(&g_e1n, 1);
    if (p < E1CAP) g_e1s[p] = s;
    unsigned m = 1u << (s & 31);
    unsigned old = atomicOr(&g_B2[s >> 5], m);
    if (!(old & m)) {
        int q = atomicAdd(&g_cnt2, 1);
        g_list2[q] = s;
        zero64(&g_agg2[(size_t)s * 64]);
    }
}
__device__ __forceinline__ void hit21v(int s, int d) {
    int p = atomicAdd(&g_e2n, 1);
    if (p < E2CAP) { g_e2s[p] = s; g_e2d[p] = d; }
    unsigned m = 1u << (s & 31);
    unsigned old = atomicOr(&g_B1[s >> 5], m);
    if (!(old & m)) {
        int q = atomicAdd(&g_cnt1, 1);
        g_list1[q] = s;
        zero64(&g_agg1[(size_t)s * 64]);
    }
}
__device__ __forceinline__ void hit10v(int s, int d) {
    int p = atomicAdd(&g_ebn, 1);
    if (p < EBCAP) { g_ebs[p] = s; g_ebd[p] = d; }
    unsigned m = 1u << (s & 31);
    unsigned old = atomicOr(&g_B0[s >> 5], m);
    if (!(old & m)) g_agg0[s] = 0.f;
}

// ---------------- scan32: dst == OUT_NODE (first kernel, no wait) ----------
__global__ void k_scan32(const int* __restrict__ src, const int* __restrict__ dst, int E) {
    int t = blockIdx.x * blockDim.x + threadIdx.x;
    int base = t * 8;
    PDL_TRIGGER();
    if (base + 7 < E) {
        int4 d0 = __ldg((const int4*)(dst + base));
        int4 d1 = __ldg((const int4*)(dst + base + 4));
        int4 s0 = __ldg((const int4*)(src + base));
        int4 s1 = __ldg((const int4*)(src + base + 4));
        int dd[8] = { d0.x, d0.y, d0.z, d0.w, d1.x, d1.y, d1.z, d1.w };
        int ss[8] = { s0.x, s0.y, s0.z, s0.w, s1.x, s1.y, s1.z, s1.w };
        #pragma unroll
        for (int i = 0; i < 8; i++) if (dd[i] == OUT_NODE) hit32v(ss[i]);
    } else {
        for (int e = base; e < E; e++)
            if (__ldg(&dst[e]) == OUT_NODE) hit32v(__ldg(&src[e]));
    }
}

// ---------------- scan21: dst in B2 (PDL: prefetch, then wait) --------------
__global__ void k_scan21(const int* __restrict__ src, const int* __restrict__ dst, int E) {
    int t = blockIdx.x * blockDim.x + threadIdx.x;
    int base = t * 8;
    bool full = (base + 7 < E);
    int4 d0, d1, s0, s1;
    if (full) {
        d0 = __ldg((const int4*)(dst + base));
        d1 = __ldg((const int4*)(dst + base + 4));
        s0 = __ldg((const int4*)(src + base));
        s1 = __ldg((const int4*)(src + base + 4));
        KEEPI4(d0); KEEPI4(d1); KEEPI4(s0); KEEPI4(s1);
    }
    PDL_TRIGGER();
    PDL_WAIT();
    if (full) {
        int dd[8] = { d0.x, d0.y, d0.z, d0.w, d1.x, d1.y, d1.z, d1.w };
        int ss[8] = { s0.x, s0.y, s0.z, s0.w, s1.x, s1.y, s1.z, s1.w };
        #pragma unroll
        for (int i = 0; i < 8; i++) if (tb(g_B2, dd[i])) hit21v(ss[i], dd[i]);
    } else {
        for (int e = base; e < E; e++) {
            int d = __ldg(&dst[e]);
            if (tb(g_B2, d)) hit21v(__ldg(&src[e]), d);
        }
    }
}

// ---------------- scan10: dst in B1 -> B0 + eb ----------------
__global__ void k_scan10(const int* __restrict__ src, const int* __restrict__ dst, int E) {
    int t = blockIdx.x * blockDim.x + threadIdx.x;
    int base = t * 8;
    bool full = (base + 7 < E);
    int4 d0, d1, s0, s1;
    if (full) {
        d0 = __ldg((const int4*)(dst + base));
        d1 = __ldg((const int4*)(dst + base + 4));
        s0 = __ldg((const int4*)(src + base));
        s1 = __ldg((const int4*)(src + base + 4));
        KEEPI4(d0); KEEPI4(d1); KEEPI4(s0); KEEPI4(s1);
    }
    PDL_TRIGGER();
    PDL_WAIT();
    if (full) {
        int dd[8] = { d0.x, d0.y, d0.z, d0.w, d1.x, d1.y, d1.z, d1.w };
        int ss[8] = { s0.x, s0.y, s0.z, s0.w, s1.x, s1.y, s1.z, s1.w };
        #pragma unroll
        for (int i = 0; i < 8; i++) if (tb(g_B1, dd[i])) hit10v(ss[i], dd[i]);
    } else {
        for (int e = base; e < E; e++) {
            int d = __ldg(&dst[e]);
            if (tb(g_B1, d)) hit10v(__ldg(&src[e]), d);
        }
    }
}

// ---------------- agg0: dst in B0 -> agg0[d] += in_feat[src] ---------------
__global__ void k_agg0(const int* __restrict__ src, const int* __restrict__ dst, int E,
                       const float* __restrict__ in_feat) {
    int t = blockIdx.x * blockDim.x + threadIdx.x;
    int base = t * 8;
    bool full = (base + 7 < E);
    int4 d0, d1, s0, s1;
    float f[8];
    if (full) {
        d0 = __ldg((const int4*)(dst + base));
        d1 = __ldg((const int4*)(dst + base + 4));
        s0 = __ldg((const int4*)(src + base));
        s1 = __ldg((const int4*)(src + base + 4));
        // in_feat gathers are input-only: prefetch pre-wait too
        f[0] = __ldg(&in_feat[s0.x]); f[1] = __ldg(&in_feat[s0.y]);
        f[2] = __ldg(&in_feat[s0.z]); f[3] = __ldg(&in_feat[s0.w]);
        f[4] = __ldg(&in_feat[s1.x]); f[5] = __ldg(&in_feat[s1.y]);
        f[6] = __ldg(&in_feat[s1.z]); f[7] = __ldg(&in_feat[s1.w]);
        KEEPI4(d0); KEEPI4(d1);
        #pragma unroll
        for (int i = 0; i < 8; i++) KEEPF(f[i]);
    }
    PDL_TRIGGER();
    PDL_WAIT();
    if (full) {
        int dd[8] = { d0.x, d0.y, d0.z, d0.w, d1.x, d1.y, d1.z, d1.w };
        #pragma unroll
        for (int i = 0; i < 8; i++)
            if (tb(g_B0, dd[i])) atomicAdd(&g_agg0[dd[i]], f[i]);
    } else {
        for (int e = base; e < E; e++) {
            int d = __ldg(&dst[e]);
            if (tb(g_B0, d)) atomicAdd(&g_agg0[d], __ldg(&in_feat[__ldg(&src[e])]));
        }
    }
}

// ---------------- agg1: agg1[d][:] += lrelu(agg0[s]*W0+b0), warp/edge -------
__global__ void k_agg1(const float* __restrict__ W0, const float* __restrict__ b0) {
    int lane = threadIdx.x & 31;
    // W0/b0 are inputs: prefetch pre-wait
    float w0a = __ldg(&W0[lane]), w0b = __ldg(&W0[lane + 32]);
    float b0a = __ldg(&b0[lane]), b0b = __ldg(&b0[lane + 32]);
    KEEPF(w0a); KEEPF(w0b); KEEPF(b0a); KEEPF(b0b);
    PDL_TRIGGER();
    PDL_WAIT();
    int n = min(g_ebn, EBCAP);
    int warp = (blockIdx.x * blockDim.x + threadIdx.x) >> 5;
    int nw = (gridDim.x * blockDim.x) >> 5;
    for (int i = warp; i < n; i += nw) {
        int s = g_ebs[i], d = g_ebd[i];
        float a0 = g_agg0[s];
        float* a = &g_agg1[(size_t)d * 64];
        atomicAdd(&a[lane],      lrelu(fmaf(a0, w0a, b0a)));
        atomicAdd(&a[lane + 32], lrelu(fmaf(a0, w0b, b0b)));
    }
}

// ---------------- h1x2: per node in list1 (warp/node) ----------------
__global__ void k_h1x2(const float* __restrict__ W1, const float* __restrict__ b1,
                       const float* __restrict__ W2) {
    PDL_TRIGGER();
    PDL_WAIT();
    int n = g_cnt1;
    int lane = threadIdx.x & 31;
    int warp = (blockIdx.x * blockDim.x + threadIdx.x) >> 5;
    int nw = (gridDim.x * blockDim.x) >> 5;
    for (int i = warp; i < n; i += nw) {
        int v = g_list1[i];
        float a0 = g_agg1[(size_t)v * 64 + lane];
        float a1 = g_agg1[(size_t)v * 64 + lane + 32];
        float h0r = __ldg(&b1[lane]);
        float h1r = __ldg(&b1[lane + 32]);
        float h2r = __ldg(&b1[lane + 64]);
        float h3r = __ldg(&b1[lane + 96]);
        #pragma unroll
        for (int k = 0; k < 64; k++) {
            float ak = __shfl_sync(0xffffffffu, (k < 32) ? a0 : a1, k & 31);
            const float* wr = &W1[k * 128];
            h0r = fmaf(ak, __ldg(&wr[lane]),      h0r);
            h1r = fmaf(ak, __ldg(&wr[lane + 32]), h1r);
            h2r = fmaf(ak, __ldg(&wr[lane + 64]), h2r);
            h3r = fmaf(ak, __ldg(&wr[lane + 96]), h3r);
        }
        float h[4] = { lrelu(h0r), lrelu(h1r), lrelu(h2r), lrelu(h3r) };
        float x0 = 0.f, x1 = 0.f;
        #pragma unroll
        for (int k = 0; k < 128; k++) {
            float hk = __shfl_sync(0xffffffffu, h[k >> 5], k & 31);
            const float* wr = &W2[k * 64];
            x0 = fmaf(hk, __ldg(&wr[lane]),      x0);
            x1 = fmaf(hk, __ldg(&wr[lane + 32]), x1);
        }
        g_x2[(size_t)v * 64 + lane]      = x0;
        g_x2[(size_t)v * 64 + lane + 32] = x1;
    }
}

// ---------------- tail: agg2 + h2x3 + final + out + cleanup (1 block) -------
__global__ void __launch_bounds__(1024, 1)
k_tail(const float* __restrict__ b2, const float* __restrict__ W3,
       const float* __restrict__ b3, float* __restrict__ out) {
    PDL_WAIT();
    int lane = threadIdx.x & 31;
    int bw = threadIdx.x >> 5;

    int n2 = min(g_e2n, E2CAP);
    for (int i = bw; i < n2; i += 32) {
        int s = g_e2s[i], d = g_e2d[i];
        float* a = &g_agg2[(size_t)d * 64];
        atomicAdd(&a[lane],      __ldcg(&g_x2[(size_t)s * 64 + lane]));
        atomicAdd(&a[lane + 32], __ldcg(&g_x2[(size_t)s * 64 + lane + 32]));
    }
    __syncthreads();

    int n3 = g_cnt2;
    for (int i = bw; i < n3; i += 32) {
        int v = g_list2[i];
        float ya = lrelu(__ldcg(&g_agg2[(size_t)v * 64 + lane])      + __ldg(&b2[lane]));
        float yb = lrelu(__ldcg(&g_agg2[(size_t)v * 64 + lane + 32]) + __ldg(&b2[lane + 32]));
        float p = fmaf(ya, __ldg(&W3[lane]), yb * __ldg(&W3[lane + 32]));
        #pragma unroll
        for (int o = 16; o; o >>= 1) p += __shfl_down_sync(0xffffffffu, p, o);
        if (lane == 0) g_x3[v] = p;
    }
    __syncthreads();

    __shared__ float red[32];
    int n1 = min(g_e1n, E1CAP);
    float s = 0.f;
    for (int i = threadIdx.x; i < n1; i += 1024) s += __ldcg(&g_x3[g_e1s[i]]);
    #pragma unroll
    for (int o = 16; o; o >>= 1) s += __shfl_down_sync(0xffffffffu, s, o);
    if (lane == 0) red[bw] = s;
    __syncthreads();
    if (threadIdx.x < 32) {
        float t = red[lane];
        #pragma unroll
        for (int o = 16; o; o >>= 1) t += __shfl_down_sync(0xffffffffu, t, o);
        if (lane == 0) out[0] = lrelu(t + __ldg(&b3[0]));
    }
    __syncthreads();

    // self-cleanup for next call (bitmaps only have bits from captured nodes)
    int c2 = g_cnt2, c1 = g_cnt1, ne = min(g_ebn, EBCAP);
    for (int i = threadIdx.x; i < c2; i += 1024) { int v = g_list2[i]; g_B2[v >> 5] = 0u; }
    for (int i = threadIdx.x; i < c1; i += 1024) { int v = g_list1[i]; g_B1[v >> 5] = 0u; }
    for (int i = threadIdx.x; i < ne; i += 1024) { int v = g_ebs[i];   g_B0[v >> 5] = 0u; }
    __syncthreads();
    if (threadIdx.x == 0) {
        g_cnt1 = 0; g_cnt2 = 0; g_e1n = 0; g_e2n = 0; g_ebn = 0;
        __threadfence();
    }
}

// ---------------------------------------------------------------------------
template <typename F, typename... A>
static void pdl_launch(F f, dim3 g, dim3 b, A... args) {
    cudaLaunchConfig_t cfg = {};
    cfg.gridDim = g;
    cfg.blockDim = b;
    cfg.dynamicSmemBytes = 0;
    cfg.stream = 0;
    cudaLaunchAttribute at;
    at.id = cudaLaunchAttributeProgrammaticStreamSerialization;
    at.val.programmaticStreamSerializationAllowed = 1;
    cfg.attrs = &at;
    cfg.numAttrs = 1;
    cudaLaunchKernelEx(&cfg, f, args...);
}

extern "C" void kernel_launch(void* const* d_in, const int* in_sizes, int n_in,
                              void* d_out, int out_size) {
    const float* in_feat = (const float*)d_in[0];
    const int*   src     = (const int*)  d_in[1];
    const int*   dst     = (const int*)  d_in[2];
    const float* W0 = (const float*)d_in[3];
    const float* b0 = (const float*)d_in[4];
    const float* W1 = (const float*)d_in[5];
    const float* b1 = (const float*)d_in[6];
    const float* W2 = (const float*)d_in[7];
    const float* b2 = (const float*)d_in[8];
    const float* W3 = (const float*)d_in[9];
    const float* b3 = (const float*)d_in[10];
    float* out = (float*)d_out;

    int E = in_sizes[1];
    int T = (E + 7) / 8;                  // one thread per 8 edges
    int sb = (T + 255) / 256;             // ~391 blocks

    k_scan32<<<sb, 256>>>(src, dst, E);   // head of chain: normal launch
    pdl_launch(k_scan21, sb, 256, src, dst, E);
    pdl_launch(k_scan10, sb, 256, src, dst, E);
    pdl_launch(k_agg0,   sb, 256, src, dst, E, in_feat);
    pdl_launch(k_agg1,   dim3(128), dim3(256), W0, b0);
    pdl_launch(k_h1x2,   dim3(64),  dim3(256), W1, b1, W2);
    pdl_launch(k_tail,   dim3(1),   dim3(1024), b2, W3, b3, out);
}